// round 2
// baseline (speedup 1.0000x reference)
#include <cuda_runtime.h>
#include <math.h>
#include <float.h>

#define NI 128
#define NC 256
#define RR 36
#define WW 48
#define DD 256

#define IMG_STR 260      // img row stride (floats): mult of 4, 260 mod 32 = 4 (bank-staggered)
#define CAPT_STR 52      // capT row stride: mult of 4 so float4/v2.b64 loads stay 16B-aligned
#define NT 192

typedef unsigned long long u64;

// ---- shared memory layout (float offsets) ----
#define OFF_IMG  0                               // img  [36][260]          9360
#define OFF_CAPT (OFF_IMG + RR*IMG_STR)          // capT [256][52]          9360..22672
#define OFF_SP   (OFF_CAPT + DD*CAPT_STR)        // Sp   [2][36][48]        22672..26128
#define OFF_A    (OFF_SP + 2*RR*WW)              // At   [36][48]           26128..27856
#define OFF_RINV (OFF_A + RR*WW)                 // rinv [36]               27856
#define OFF_RS   (OFF_RINV + RR)                 // rs   [48]               27892
#define OFF_CN   (OFF_RS + WW)                   // capnS[48]               27940
#define SMEM_FLOATS (OFF_CN + WW)                // 27988 floats = 111952 B

__device__ float g_capnorm[NC * WW];

// ---- Blackwell packed f32x2 helpers ----
__device__ __forceinline__ u64 dup2(float x) {
    u64 r; asm("mov.b64 %0, {%1, %1};" : "=l"(r) : "f"(x)); return r;
}
__device__ __forceinline__ void ffma2(u64& d, u64 a, u64 b) {
    asm("fma.rn.f32x2 %0, %1, %2, %0;" : "+l"(d) : "l"(a), "l"(b));
}
__device__ __forceinline__ float2 unpk(u64 v) {
    float2 r; asm("mov.b64 {%0, %1}, %2;" : "=f"(r.x), "=f"(r.y) : "l"(v)); return r;
}

// ---- pre-kernel: per-(caption,word) L2 norms, computed once ----
__global__ void capnorm_kernel(const float* __restrict__ captions) {
    int c = blockIdx.x, w = threadIdx.x;
    const float4* p = (const float4*)(captions + ((size_t)c * WW + w) * DD);
    float s = 0.f;
    #pragma unroll 8
    for (int j = 0; j < DD / 4; ++j) {
        float4 v = p[j];
        s += v.x * v.x + v.y * v.y + v.z * v.z + v.w * v.w;
    }
    g_capnorm[c * WW + w] = sqrtf(s);
}

extern __shared__ float sm[];

__global__ void __launch_bounds__(NT, 2)
scan_kernel(const float* __restrict__ images,
            const float* __restrict__ captions,
            float* __restrict__ out)
{
    const int c = blockIdx.x;
    const int i = blockIdx.y;
    const int t = threadIdx.x;

    float* img   = sm + OFF_IMG;
    float* capT  = sm + OFF_CAPT;
    float* Sp    = sm + OFF_SP;
    float* At    = sm + OFF_A;
    float* rinv  = sm + OFF_RINV;
    float* rs    = sm + OFF_RS;
    float* capnS = sm + OFF_CN;

    // ================= Phase 1: load tiles =================
    {
        const float4* gi = (const float4*)(images + (size_t)i * RR * DD);
        for (int idx = t; idx < RR * DD / 4; idx += NT) {
            float4 v = gi[idx];
            int r = idx >> 6;
            int d = (idx & 63) << 2;
            *(float4*)(img + r * IMG_STR + d) = v;
        }
        const float4* gc = (const float4*)(captions + (size_t)c * WW * DD);
        for (int idx = t; idx < WW * DD / 4; idx += NT) {
            float4 v = gc[idx];
            int w = idx >> 6;
            int d = (idx & 63) << 2;
            capT[(d + 0) * CAPT_STR + w] = v.x;
            capT[(d + 1) * CAPT_STR + w] = v.y;
            capT[(d + 2) * CAPT_STR + w] = v.z;
            capT[(d + 3) * CAPT_STR + w] = v.w;
        }
        if (t < WW) capnS[t] = g_capnorm[c * WW + t];
    }
    __syncthreads();

    // ====== Phase 2: S[r][w] = sum_d img[r][d]*cap[w][d] (FFMA2, pairs along w) ======
    // 144 active threads = 2 k-slices x (12 r-groups x 6 w-groups); tile 3r x 8w
    if (t < 144) {
        const int ks = t / 72;
        const int u  = t % 72;
        const int wg = u % 6;
        const int rg = u / 6;
        const int r0 = rg * 3, w0 = wg * 8;

        u64 acc[3][4];
        #pragma unroll
        for (int jr = 0; jr < 3; jr++)
            #pragma unroll
            for (int e = 0; e < 4; e++) acc[jr][e] = 0ull;

        const float* ip = img + r0 * IMG_STR + ks * 128;
        const float* cp = capT + (ks * 128) * CAPT_STR + w0;

        #pragma unroll 2
        for (int d = 0; d < 128; ++d) {
            ulonglong2 cA = *(const ulonglong2*)(cp);
            ulonglong2 cB = *(const ulonglong2*)(cp + 4);
            u64 cv0 = cA.x, cv1 = cA.y, cv2 = cB.x, cv3 = cB.y;
            #pragma unroll
            for (int jr = 0; jr < 3; jr++) {
                u64 iv = dup2(ip[jr * IMG_STR]);
                ffma2(acc[jr][0], iv, cv0);
                ffma2(acc[jr][1], iv, cv1);
                ffma2(acc[jr][2], iv, cv2);
                ffma2(acc[jr][3], iv, cv3);
            }
            ip += 1;
            cp += CAPT_STR;
        }
        float* sp = Sp + ks * (RR * WW);
        #pragma unroll
        for (int jr = 0; jr < 3; jr++)
            #pragma unroll
            for (int e = 0; e < 4; e++)
                *(u64*)(sp + (r0 + jr) * WW + w0 + 2 * e) = acc[jr][e];
    }
    __syncthreads();

    // ====== Phase 3a: combine k-slices + leaky_relu + row sumsq (all 192 thr) ======
    {
        const int r = t >> 2, l = t & 3;
        float ss = 0.f;
        if (r < RR) {
            float* s0 = Sp + r * WW + l * 12;
            float* s1 = s0 + RR * WW;
            #pragma unroll
            for (int q = 0; q < 3; q++) {
                float4 a = *(float4*)(s0 + 4 * q);
                float4 b = *(float4*)(s1 + 4 * q);
                float v;
                v = a.x + b.x; v = (v >= 0.f) ? v : 0.1f * v; a.x = v; ss = fmaf(v, v, ss);
                v = a.y + b.y; v = (v >= 0.f) ? v : 0.1f * v; a.y = v; ss = fmaf(v, v, ss);
                v = a.z + b.z; v = (v >= 0.f) ? v : 0.1f * v; a.z = v; ss = fmaf(v, v, ss);
                v = a.w + b.w; v = (v >= 0.f) ? v : 0.1f * v; a.w = v; ss = fmaf(v, v, ss);
                *(float4*)(s0 + 4 * q) = a;
            }
        }
        ss += __shfl_xor_sync(0xffffffffu, ss, 1);
        ss += __shfl_xor_sync(0xffffffffu, ss, 2);
        if (l == 0 && r < RR) rinv[r] = 1.f / (sqrtf(ss) + 1e-8f);
    }
    __syncthreads();

    // ====== Phase 3b: softmax over r per w (max-free: |9*s|<=9), write At[r][w] ======
    {
        const int w = t >> 2, l = t & 3;
        float e[9];
        float s = 0.f;
        #pragma unroll
        for (int jj = 0; jj < 9; jj++) {
            int r = l * 9 + jj;
            float v = 9.f * Sp[r * WW + w] * rinv[r];
            e[jj] = __expf(v);
            s += e[jj];
        }
        s += __shfl_xor_sync(0xffffffffu, s, 1);
        s += __shfl_xor_sync(0xffffffffu, s, 2);
        float is = 1.f / s;
        #pragma unroll
        for (int jj = 0; jj < 9; jj++) {
            int r = l * 9 + jj;
            At[r * WW + w] = e[jj] * is;
        }
    }
    __syncthreads();

    // ====== Phase 4: wctx = A @ img (FFMA2, pairs along d) + fused cosine partials ======
    // 192 thr = 12 w-groups x 16 d-groups; per-thread 4w x 8d, 2 chunks over d
    {
        const int wg = t >> 4, dg = t & 15;
        const int w0 = wg * 4;
        float pp12[4] = {0.f, 0.f, 0.f, 0.f};
        float ppsq[4] = {0.f, 0.f, 0.f, 0.f};

        #pragma unroll
        for (int chunk = 0; chunk < 2; ++chunk) {
            const int d0 = chunk * 128 + dg * 8;
            u64 acc[4][4];
            #pragma unroll
            for (int j = 0; j < 4; j++)
                #pragma unroll
                for (int e = 0; e < 4; e++) acc[j][e] = 0ull;

            const float* ap = At + w0;
            const float* ipb = img + d0;
            #pragma unroll 2
            for (int k = 0; k < RR; ++k) {
                float4 a4 = *(const float4*)(ap);
                u64 a0 = dup2(a4.x), a1 = dup2(a4.y), a2 = dup2(a4.z), a3 = dup2(a4.w);
                ulonglong2 vA = *(const ulonglong2*)(ipb);
                ulonglong2 vB = *(const ulonglong2*)(ipb + 4);
                u64 iv0 = vA.x, iv1 = vA.y, iv2 = vB.x, iv3 = vB.y;
                ffma2(acc[0][0], a0, iv0); ffma2(acc[0][1], a0, iv1);
                ffma2(acc[0][2], a0, iv2); ffma2(acc[0][3], a0, iv3);
                ffma2(acc[1][0], a1, iv0); ffma2(acc[1][1], a1, iv1);
                ffma2(acc[1][2], a1, iv2); ffma2(acc[1][3], a1, iv3);
                ffma2(acc[2][0], a2, iv0); ffma2(acc[2][1], a2, iv1);
                ffma2(acc[2][2], a2, iv2); ffma2(acc[2][3], a2, iv3);
                ffma2(acc[3][0], a3, iv0); ffma2(acc[3][1], a3, iv1);
                ffma2(acc[3][2], a3, iv2); ffma2(acc[3][3], a3, iv3);
                ap += WW;
                ipb += IMG_STR;
            }
            // cosine partials for this 8-d slice
            #pragma unroll
            for (int j = 0; j < 4; j++) {
                const int w = w0 + j;
                #pragma unroll
                for (int e = 0; e < 4; e++) {
                    float2 v = unpk(acc[j][e]);
                    float c0 = capT[(d0 + 2 * e) * CAPT_STR + w];
                    float c1 = capT[(d0 + 2 * e + 1) * CAPT_STR + w];
                    pp12[j] = fmaf(v.x, c0, pp12[j]);
                    pp12[j] = fmaf(v.y, c1, pp12[j]);
                    ppsq[j] = fmaf(v.x, v.x, ppsq[j]);
                    ppsq[j] = fmaf(v.y, v.y, ppsq[j]);
                }
            }
        }
        // reduce over the 16 d-group lanes (contiguous within warp)
        #pragma unroll
        for (int off = 8; off; off >>= 1) {
            #pragma unroll
            for (int j = 0; j < 4; j++) {
                pp12[j] += __shfl_down_sync(0xffffffffu, pp12[j], off, 16);
                ppsq[j] += __shfl_down_sync(0xffffffffu, ppsq[j], off, 16);
            }
        }
        if (dg == 0) {
            #pragma unroll
            for (int j = 0; j < 4; j++) {
                const int w = w0 + j;
                float w2 = sqrtf(ppsq[j]);
                float denom = fmaxf(capnS[w] * w2, 1e-8f);
                rs[w] = (pp12[j] / denom) * 6.f;
            }
        }
    }
    __syncthreads();

    // ====== Phase 5: LogSumExp over 48 words (max-free: |rs|<=6) ======
    if (t < 32) {
        float s = __expf(rs[t]);
        if (t < 16) s += __expf(rs[32 + t]);
        #pragma unroll
        for (int off = 16; off; off >>= 1)
            s += __shfl_xor_sync(0xffffffffu, s, off);
        if (t == 0)
            out[(size_t)i * NC + c] = logf(s) * (1.f / 6.f);
    }
}

extern "C" void kernel_launch(void* const* d_in, const int* in_sizes, int n_in,
                              void* d_out, int out_size)
{
    const float* images   = (const float*)d_in[0];   // (128, 36, 256) fp32
    const float* captions = (const float*)d_in[1];   // (256, 48, 256) fp32
    float* out = (float*)d_out;                       // (128, 256) fp32

    cudaFuncSetAttribute(scan_kernel,
                         cudaFuncAttributeMaxDynamicSharedMemorySize,
                         SMEM_FLOATS * (int)sizeof(float));

    capnorm_kernel<<<NC, WW>>>(captions);

    dim3 grid(NC, NI);
    scan_kernel<<<grid, NT, SMEM_FLOATS * sizeof(float)>>>(images, captions, out);
}

// round 4
// speedup vs baseline: 2.0128x; 2.0128x over previous
#include <cuda_runtime.h>
#include <math.h>
#include <float.h>

#define NI 128
#define NC 256
#define RR 36
#define WW 48
#define DD 256

#define IMG_STR 260      // img row stride: (3rg+jr)*260 mod 32 = 4*(3rg+jr) -> distinct per rg
#define CAPT_STR 50      // even (8B-aligned u64 rows); 6*wg starts give disjoint bank pairs
#define AT_STR 36        // w*36 mod 32 = 4w; float4 aligned
#define NT 192

typedef unsigned long long u64;

// ---- shared memory layout (float offsets) ----
#define OFF_IMG  0                               // img  [36][260]           9360
#define OFF_CAPT (OFF_IMG + RR*IMG_STR)          // capT [256][50]           -> 22160
#define OFF_SP   (OFF_CAPT + DD*CAPT_STR)        // Sp   [2][36][48]         -> 25616
#define OFF_G    (OFF_SP + RR*WW)                // G[36*36]=1296 aliases Sp[1] (dead after 3a)
#define OFF_AT   (OFF_SP + 2*RR*WW)              // At   [48][36]            -> 27344
#define OFF_RINV (OFF_AT + WW*AT_STR)            // rinv [36]
#define OFF_RS   (OFF_RINV + RR)                 // rs   [48]
#define OFF_CN   (OFF_RS + WW)                   // capn [48]
#define SMEM_FLOATS (OFF_CN + WW)                // 27476 floats = 109904 B

__device__ float g_capnorm[NC * WW];
__device__ float g_gram[NI * RR * RR];

// ---- Blackwell packed f32x2 helpers ----
__device__ __forceinline__ u64 dup2(float x) {
    u64 r; asm("mov.b64 %0, {%1, %1};" : "=l"(r) : "f"(x)); return r;
}
__device__ __forceinline__ void ffma2(u64& d, u64 a, u64 b) {
    asm("fma.rn.f32x2 %0, %1, %2, %0;" : "+l"(d) : "l"(a), "l"(b));
}

// ---- pre-kernel 1: per-(caption,word) L2 norms ----
__global__ void capnorm_kernel(const float* __restrict__ captions) {
    int c = blockIdx.x, w = threadIdx.x;
    const float4* p = (const float4*)(captions + ((size_t)c * WW + w) * DD);
    float s = 0.f;
    #pragma unroll 8
    for (int j = 0; j < DD / 4; ++j) {
        float4 v = p[j];
        s += v.x * v.x + v.y * v.y + v.z * v.z + v.w * v.w;
    }
    g_capnorm[c * WW + w] = sqrtf(s);
}

// ---- pre-kernel 2: per-image Gram matrix G = img @ img^T (36x36) ----
__global__ void gram_kernel(const float* __restrict__ images) {
    __shared__ float s_img[RR * IMG_STR];
    const int i = blockIdx.x;
    const float4* src = (const float4*)(images + (size_t)i * RR * DD);
    for (int idx = threadIdx.x; idx < RR * DD / 4; idx += blockDim.x) {
        float4 v = src[idx];
        int r = idx >> 6;
        int d = (idx & 63) << 2;
        *(float4*)(s_img + r * IMG_STR + d) = v;
    }
    __syncthreads();
    for (int e = threadIdx.x; e < RR * RR; e += blockDim.x) {
        int k1 = e / RR, k2 = e % RR;
        const float4* p = (const float4*)(s_img + k1 * IMG_STR);
        const float4* q = (const float4*)(s_img + k2 * IMG_STR);
        float s = 0.f;
        #pragma unroll 8
        for (int d = 0; d < DD / 4; ++d) {
            float4 a = p[d], b = q[d];
            s = fmaf(a.x, b.x, s); s = fmaf(a.y, b.y, s);
            s = fmaf(a.z, b.z, s); s = fmaf(a.w, b.w, s);
        }
        g_gram[(size_t)i * RR * RR + e] = s;
    }
}

extern __shared__ float sm[];

__global__ void __launch_bounds__(NT, 2)
scan_kernel(const float* __restrict__ images,
            const float* __restrict__ captions,
            float* __restrict__ out)
{
    const int c = blockIdx.x;
    const int i = blockIdx.y;
    const int t = threadIdx.x;

    float* img   = sm + OFF_IMG;
    float* capT  = sm + OFF_CAPT;
    float* Sp    = sm + OFF_SP;     // Sp[0]=raw S (after 3a combine); Sp[1]=k-split partial
    float* Gm    = sm + OFF_G;      // aliases Sp[1] after phase 3a
    float* At    = sm + OFF_AT;     // softmax weights [48][36]
    float* rinv  = sm + OFF_RINV;
    float* rs    = sm + OFF_RS;
    float* capnS = sm + OFF_CN;

    // ================= Phase 1: load tiles =================
    {
        const float4* gi = (const float4*)(images + (size_t)i * RR * DD);
        for (int idx = t; idx < RR * DD / 4; idx += NT) {
            float4 v = gi[idx];
            int r = idx >> 6;
            int d = (idx & 63) << 2;
            *(float4*)(img + r * IMG_STR + d) = v;
        }
        const float4* gc = (const float4*)(captions + (size_t)c * WW * DD);
        for (int idx = t; idx < WW * DD / 4; idx += NT) {
            float4 v = gc[idx];
            int w = idx >> 6;
            int d = (idx & 63) << 2;
            capT[(d + 0) * CAPT_STR + w] = v.x;
            capT[(d + 1) * CAPT_STR + w] = v.y;
            capT[(d + 2) * CAPT_STR + w] = v.z;
            capT[(d + 3) * CAPT_STR + w] = v.w;
        }
        if (t < WW) capnS[t] = g_capnorm[c * WW + t];
    }
    __syncthreads();

    // ====== Phase 2: S_raw[r][w] = sum_d img[r][d]*cap[w][d] (FFMA2 pairs along w) ======
    // 192 thr = 2 k-slices x (12 rg x 8 wg); per-thread tile 3r x 6w
    {
        const int ks = t / 96;          // warps 0-2: ks=0, warps 3-5: ks=1
        const int u  = t % 96;
        const int wg = u & 7;
        const int rg = u >> 3;
        const int r0 = rg * 3, w0 = wg * 6;

        u64 acc[3][3];
        #pragma unroll
        for (int jr = 0; jr < 3; jr++)
            #pragma unroll
            for (int e = 0; e < 3; e++) acc[jr][e] = 0ull;

        const float* ip = img + r0 * IMG_STR + ks * 128;
        const float* cp = capT + (ks * 128) * CAPT_STR + w0;

        #pragma unroll 4
        for (int d = 0; d < 128; ++d) {
            u64 cv0 = *(const u64*)(cp);
            u64 cv1 = *(const u64*)(cp + 2);
            u64 cv2 = *(const u64*)(cp + 4);
            #pragma unroll
            for (int jr = 0; jr < 3; jr++) {
                u64 iv = dup2(ip[jr * IMG_STR]);
                ffma2(acc[jr][0], iv, cv0);
                ffma2(acc[jr][1], iv, cv1);
                ffma2(acc[jr][2], iv, cv2);
            }
            ip += 1;
            cp += CAPT_STR;
        }
        float* sp = Sp + ks * (RR * WW);
        #pragma unroll
        for (int jr = 0; jr < 3; jr++)
            #pragma unroll
            for (int e = 0; e < 3; e++)
                *(u64*)(sp + (r0 + jr) * WW + w0 + 2 * e) = acc[jr][e];
    }
    __syncthreads();

    // ====== Phase 3a: combine k-slices into raw S (Sp[0]); rinv from leaky rows ======
    // ALL 192 threads execute (shuffles must be warp-converged); r>=36 lanes idle.
    {
        const int r = t >> 2, l = t & 3;
        const bool act = (r < RR);
        float ss = 0.f;
        if (act) {
            float* s0 = Sp + r * WW + l * 12;
            float* s1 = s0 + RR * WW;
            #pragma unroll
            for (int q = 0; q < 3; q++) {
                float4 a = *(float4*)(s0 + 4 * q);
                float4 b = *(float4*)(s1 + 4 * q);
                a.x += b.x; a.y += b.y; a.z += b.z; a.w += b.w;
                *(float4*)(s0 + 4 * q) = a;                      // raw S
                float v;
                v = (a.x >= 0.f) ? a.x : 0.1f * a.x; ss = fmaf(v, v, ss);
                v = (a.y >= 0.f) ? a.y : 0.1f * a.y; ss = fmaf(v, v, ss);
                v = (a.z >= 0.f) ? a.z : 0.1f * a.z; ss = fmaf(v, v, ss);
                v = (a.w >= 0.f) ? a.w : 0.1f * a.w; ss = fmaf(v, v, ss);
            }
        }
        ss += __shfl_xor_sync(0xffffffffu, ss, 1);
        ss += __shfl_xor_sync(0xffffffffu, ss, 2);
        if (act && l == 0) rinv[r] = 1.f / (sqrtf(ss) + 1e-8f);
    }
    __syncthreads();

    // ====== G load (into Sp[1] space, dead now) overlapped with Phase 3b ======
    float gtmp[7];
    {
        const float* gsrc = g_gram + (size_t)i * RR * RR;
        #pragma unroll
        for (int q = 0; q < 7; q++) {
            int idx = t + q * NT;
            if (idx < RR * RR) gtmp[q] = gsrc[idx];
        }
    }

    // ====== Phase 3b: softmax over r per w (max-free: |9*shat|<=9) + w12 fused ======
    const int w3 = t >> 2, l3 = t & 3;    // 48 w x 4 lanes (all 192 threads)
    float a9[9];
    float w12v;
    {
        float e9[9];
        float s = 0.f, w12p = 0.f;
        #pragma unroll
        for (int jj = 0; jj < 9; jj++) {
            int r = l3 * 9 + jj;
            float sraw = Sp[r * WW + w3];
            float v = (sraw >= 0.f) ? sraw : 0.1f * sraw;
            float e = __expf(9.f * v * rinv[r]);
            e9[jj] = e;
            s += e;
            w12p = fmaf(e, sraw, w12p);
        }
        s += __shfl_xor_sync(0xffffffffu, s, 1);
        s += __shfl_xor_sync(0xffffffffu, s, 2);
        w12p += __shfl_xor_sync(0xffffffffu, w12p, 1);
        w12p += __shfl_xor_sync(0xffffffffu, w12p, 2);
        float is = 1.f / s;
        w12v = w12p * is;
        #pragma unroll
        for (int jj = 0; jj < 9; jj++) {
            float a = e9[jj] * is;
            a9[jj] = a;
            At[w3 * AT_STR + l3 * 9 + jj] = a;
        }
    }
    // stage G into smem (loads issued before 3b -> latency hidden)
    {
        #pragma unroll
        for (int q = 0; q < 7; q++) {
            int idx = t + q * NT;
            if (idx < RR * RR) Gm[idx] = gtmp[q];
        }
    }
    __syncthreads();

    // ====== Phase 4': w2sq[w] = A[w,:] G A[w,:]^T (quadratic form) ======
    {
        float4 av[9];
        const float4* apv = (const float4*)(At + w3 * AT_STR);
        #pragma unroll
        for (int q = 0; q < 9; q++) av[q] = apv[q];

        float w2p = 0.f;
        #pragma unroll
        for (int jj = 0; jj < 9; jj++) {
            const int k = l3 * 9 + jj;
            const float4* gp = (const float4*)(Gm + k * RR);
            float uacc = 0.f;
            #pragma unroll
            for (int q = 0; q < 9; q++) {
                float4 g = gp[q], a = av[q];
                uacc = fmaf(g.x, a.x, uacc);
                uacc = fmaf(g.y, a.y, uacc);
                uacc = fmaf(g.z, a.z, uacc);
                uacc = fmaf(g.w, a.w, uacc);
            }
            w2p = fmaf(a9[jj], uacc, w2p);
        }
        w2p += __shfl_xor_sync(0xffffffffu, w2p, 1);
        w2p += __shfl_xor_sync(0xffffffffu, w2p, 2);
        if (l3 == 0) {
            float w2 = sqrtf(fmaxf(w2p, 0.f));
            float denom = fmaxf(capnS[w3] * w2, 1e-8f);
            rs[w3] = (w12v / denom) * 6.f;
        }
    }
    __syncthreads();

    // ====== Phase 5: LogSumExp over 48 words (max-free: |rs|<=6) ======
    if (t < 32) {
        float s = __expf(rs[t]);
        if (t < 16) s += __expf(rs[32 + t]);
        #pragma unroll
        for (int off = 16; off; off >>= 1)
            s += __shfl_xor_sync(0xffffffffu, s, off);
        if (t == 0)
            out[(size_t)i * NC + c] = logf(s) * (1.f / 6.f);
    }
}

extern "C" void kernel_launch(void* const* d_in, const int* in_sizes, int n_in,
                              void* d_out, int out_size)
{
    const float* images   = (const float*)d_in[0];   // (128, 36, 256) fp32
    const float* captions = (const float*)d_in[1];   // (256, 48, 256) fp32
    float* out = (float*)d_out;                       // (128, 256) fp32

    cudaFuncSetAttribute(scan_kernel,
                         cudaFuncAttributeMaxDynamicSharedMemorySize,
                         SMEM_FLOATS * (int)sizeof(float));

    capnorm_kernel<<<NC, WW>>>(captions);
    gram_kernel<<<NI, 256>>>(images);

    dim3 grid(NC, NI);
    scan_kernel<<<grid, NT, SMEM_FLOATS * sizeof(float)>>>(images, captions, out);
}

// round 6
// speedup vs baseline: 4.3840x; 2.1781x over previous
#include <cuda_runtime.h>
#include <cuda_bf16.h>
#include <math.h>
#include <float.h>
#include <stdint.h>

#define NI 128
#define NC 256
#define RR 36
#define WW 48
#define DD 256

#define MROWS (NI*RR)     // 4608
#define NCOLS (NC*WW)     // 12288

// ---------------- device scratch ----------------
__device__ __align__(16) __nv_bfloat16 g_Ahi[MROWS * DD];
__device__ __align__(16) __nv_bfloat16 g_Alo[MROWS * DD];
__device__ __align__(16) __nv_bfloat16 g_Bhi[NCOLS * DD];
__device__ __align__(16) __nv_bfloat16 g_Blo[NCOLS * DD];
__device__ __align__(16) float g_S[(size_t)MROWS * NCOLS];   // 226 MB
__device__ float g_capnorm[NC * WW];
__device__ __align__(16) float g_gram[NI * RR * RR];

// ---------------- PTX helpers (baseline sm_80 features only) ----------------
__device__ __forceinline__ uint32_t smem_u32(const void* p) {
    uint32_t a;
    asm("{ .reg .u64 t; cvta.to.shared.u64 t, %1; cvt.u32.u64 %0, t; }" : "=r"(a) : "l"(p));
    return a;
}
__device__ __forceinline__ void cpa16(uint32_t dst, const void* src) {
    asm volatile("cp.async.cg.shared.global [%0], [%1], 16;" :: "r"(dst), "l"(src));
}
__device__ __forceinline__ void cpa_commit() {
    asm volatile("cp.async.commit_group;" ::: "memory");
}
template<int N> __device__ __forceinline__ void cpa_wait() {
    asm volatile("cp.async.wait_group %0;" :: "n"(N) : "memory");
}
__device__ __forceinline__ void ldsm4(uint32_t* r, uint32_t addr) {
    asm volatile("ldmatrix.sync.aligned.m8n8.x4.shared.b16 {%0,%1,%2,%3}, [%4];"
                 : "=r"(r[0]), "=r"(r[1]), "=r"(r[2]), "=r"(r[3]) : "r"(addr));
}
__device__ __forceinline__ void mma_bf16(float* d, const uint32_t* a, const uint32_t* b) {
    asm volatile(
        "mma.sync.aligned.m16n8k16.row.col.f32.bf16.bf16.f32 "
        "{%0,%1,%2,%3}, {%4,%5,%6,%7}, {%8,%9}, {%0,%1,%2,%3};"
        : "+f"(d[0]), "+f"(d[1]), "+f"(d[2]), "+f"(d[3])
        : "r"(a[0]), "r"(a[1]), "r"(a[2]), "r"(a[3]), "r"(b[0]), "r"(b[1]));
}

// ---------------- pre-kernels ----------------
__global__ void decomp_kernel(const float* __restrict__ images,
                              const float* __restrict__ captions) {
    int stride = gridDim.x * blockDim.x;
    int g = blockIdx.x * blockDim.x + threadIdx.x;
    for (int idx = g; idx < MROWS * DD; idx += stride) {
        float x = images[idx];
        __nv_bfloat16 h = __float2bfloat16(x);
        g_Ahi[idx] = h;
        g_Alo[idx] = __float2bfloat16(x - __bfloat162float(h));
    }
    for (int idx = g; idx < NCOLS * DD; idx += stride) {
        float x = captions[idx];
        __nv_bfloat16 h = __float2bfloat16(x);
        g_Bhi[idx] = h;
        g_Blo[idx] = __float2bfloat16(x - __bfloat162float(h));
    }
}

__global__ void capnorm_kernel(const float* __restrict__ captions) {
    int c = blockIdx.x, w = threadIdx.x;
    const float4* p = (const float4*)(captions + ((size_t)c * WW + w) * DD);
    float s = 0.f;
    #pragma unroll 8
    for (int j = 0; j < DD / 4; ++j) {
        float4 v = p[j];
        s += v.x * v.x + v.y * v.y + v.z * v.z + v.w * v.w;
    }
    g_capnorm[c * WW + w] = sqrtf(s);
}

#define GIMG_STR 260
__global__ void gram_kernel(const float* __restrict__ images) {
    __shared__ float s_img[RR * GIMG_STR];
    const int i = blockIdx.x;
    const float4* src = (const float4*)(images + (size_t)i * RR * DD);
    for (int idx = threadIdx.x; idx < RR * DD / 4; idx += blockDim.x) {
        float4 v = src[idx];
        int r = idx >> 6;
        int d = (idx & 63) << 2;
        *(float4*)(s_img + r * GIMG_STR + d) = v;
    }
    __syncthreads();
    for (int e = threadIdx.x; e < RR * RR; e += blockDim.x) {
        int k1 = e / RR, k2 = e % RR;
        const float4* p = (const float4*)(s_img + k1 * GIMG_STR);
        const float4* q = (const float4*)(s_img + k2 * GIMG_STR);
        float s = 0.f;
        #pragma unroll 8
        for (int d = 0; d < DD / 4; ++d) {
            float4 a = p[d], b = q[d];
            s = fmaf(a.x, b.x, s); s = fmaf(a.y, b.y, s);
            s = fmaf(a.z, b.z, s); s = fmaf(a.w, b.w, s);
        }
        g_gram[(size_t)i * RR * RR + e] = s;
    }
}

// ---------------- GEMM: S_all = A @ B^T via mma.sync bf16 3-term split ----------------
// CTA tile 128x128, 8 warps in 2(m) x 4(n), warp tile 64x32.
// K chunks of 32, double-buffered cp.async. smem rows: 32 bf16 + 8 pad = 80 B.
#define GT 256
#define TSTR_B 80
#define TILE_BYTES (128 * TSTR_B)              // 10240
#define GSMEM_TOTAL (8 * TILE_BYTES)           // 81920 (2 buffers x 4 tiles)

__global__ void __launch_bounds__(GT, 2) gemm_kernel() {
    extern __shared__ char smem[];
    const uint32_t sb = smem_u32(smem);
    const int tid = threadIdx.x;
    const int wid = tid >> 5, lane = tid & 31;
    const int ntile = blockIdx.x;   // 0..95
    const int mtile = blockIdx.y;   // 0..35

    const __nv_bfloat16* gsrc[4] = {
        g_Ahi + (size_t)(mtile * 128) * DD,
        g_Alo + (size_t)(mtile * 128) * DD,
        g_Bhi + (size_t)(ntile * 128) * DD,
        g_Blo + (size_t)(ntile * 128) * DD
    };

    // per-chunk load: 4 tiles x 128 rows x 4 x 16B = 2048 transfers, 8/thread
    auto issue = [&](int kc) {
        const uint32_t bufbase = sb + (uint32_t)(kc & 1) * 4 * TILE_BYTES;
        #pragma unroll
        for (int p = 0; p < 8; p++) {
            int idx = tid + p * GT;
            int tile = idx >> 9, rem = idx & 511;
            int r = rem >> 2, j = rem & 3;
            const __nv_bfloat16* src = gsrc[tile] + (size_t)r * DD + kc * 32 + j * 8;
            uint32_t dst = bufbase + tile * TILE_BYTES + r * TSTR_B + j * 16;
            cpa16(dst, src);
        }
        cpa_commit();
    };

    const int wm = wid >> 2, wn = wid & 3;

    float acc[4][4][4];
    #pragma unroll
    for (int f = 0; f < 4; f++)
        #pragma unroll
        for (int nf = 0; nf < 4; nf++)
            #pragma unroll
            for (int e = 0; e < 4; e++) acc[f][nf][e] = 0.f;

    issue(0);
    for (int kc = 0; kc < 8; kc++) {
        if (kc < 7) { issue(kc + 1); cpa_wait<1>(); }
        else        { cpa_wait<0>(); }
        __syncthreads();

        const uint32_t abase = sb + (uint32_t)(kc & 1) * 4 * TILE_BYTES;
        const uint32_t bbase = abase + 2 * TILE_BYTES;

        #pragma unroll
        for (int s = 0; s < 2; s++) {
            // B fragments: 2 x ldmatrix.x4 per matrix (n-groups of 16)
            uint32_t bh[8], bl[8];
            {
                int bn = wn * 32 + (lane & 7) + ((lane >> 4) << 3);
                uint32_t bcol = s * 32 + ((lane >> 3) & 1) * 16;
                #pragma unroll
                for (int g = 0; g < 2; g++) {
                    uint32_t addr = bbase + (uint32_t)(bn + g * 16) * TSTR_B + bcol;
                    ldsm4(&bh[g * 4], addr);
                    ldsm4(&bl[g * 4], addr + TILE_BYTES);
                }
            }
            // A fragments per m-frag, 3-term mma
            int ar = wm * 64 + (lane & 15);
            uint32_t acol = s * 32 + (lane >> 4) * 16;
            #pragma unroll
            for (int f = 0; f < 4; f++) {
                uint32_t aaddr = abase + (uint32_t)(ar + f * 16) * TSTR_B + acol;
                uint32_t ah[4], al[4];
                ldsm4(ah, aaddr);
                ldsm4(al, aaddr + TILE_BYTES);
                #pragma unroll
                for (int nf = 0; nf < 4; nf++) {
                    mma_bf16(acc[f][nf], ah, &bh[nf * 2]);   // hi*hi
                    mma_bf16(acc[f][nf], ah, &bl[nf * 2]);   // hi*lo
                    mma_bf16(acc[f][nf], al, &bh[nf * 2]);   // lo*hi
                }
            }
        }
        __syncthreads();
    }

    // store accumulators (float2 pairs)
    float* obase = g_S + (size_t)(mtile * 128) * NCOLS + ntile * 128;
    const int r0 = wm * 64 + (lane >> 2);
    const int c0 = wn * 32 + (lane & 3) * 2;
    #pragma unroll
    for (int f = 0; f < 4; f++) {
        #pragma unroll
        for (int nf = 0; nf < 4; nf++) {
            int r = r0 + f * 16, cc = c0 + nf * 8;
            float2 v0 = { acc[f][nf][0], acc[f][nf][1] };
            float2 v1 = { acc[f][nf][2], acc[f][nf][3] };
            *(float2*)(obase + (size_t)r * NCOLS + cc) = v0;
            *(float2*)(obase + (size_t)(r + 8) * NCOLS + cc) = v1;
        }
    }
}

// ---------------- epilogue kernel (R4-validated math) ----------------
#define NT 192
#define AT_STR 36
__global__ void __launch_bounds__(NT) epi_kernel(float* __restrict__ out) {
    __shared__ float Sp[RR * WW];
    __shared__ float Gm[RR * RR];
    __shared__ float At[WW * AT_STR];
    __shared__ float rinv[RR];
    __shared__ float rs[WW];
    __shared__ float capnS[WW];

    const int c = blockIdx.x, i = blockIdx.y, t = threadIdx.x;

    {
        const float* srow = g_S + (size_t)(i * RR) * NCOLS + c * WW;
        for (int idx = t; idx < RR * 12; idx += NT) {
            int r = idx / 12, q = idx % 12;
            *(float4*)(Sp + r * WW + q * 4) = *(const float4*)(srow + (size_t)r * NCOLS + q * 4);
        }
        const float* gsrc = g_gram + (size_t)i * RR * RR;
        for (int idx = t; idx < RR * RR; idx += NT) Gm[idx] = gsrc[idx];
        if (t < WW) capnS[t] = g_capnorm[c * WW + t];
    }
    __syncthreads();

    // rinv from leaky rows
    {
        const int r = t >> 2, l = t & 3;
        const bool act = (r < RR);
        float ss = 0.f;
        if (act) {
            const float* s0 = Sp + r * WW + l * 12;
            #pragma unroll
            for (int q = 0; q < 3; q++) {
                float4 a = *(const float4*)(s0 + 4 * q);
                float v;
                v = (a.x >= 0.f) ? a.x : 0.1f * a.x; ss = fmaf(v, v, ss);
                v = (a.y >= 0.f) ? a.y : 0.1f * a.y; ss = fmaf(v, v, ss);
                v = (a.z >= 0.f) ? a.z : 0.1f * a.z; ss = fmaf(v, v, ss);
                v = (a.w >= 0.f) ? a.w : 0.1f * a.w; ss = fmaf(v, v, ss);
            }
        }
        ss += __shfl_xor_sync(0xffffffffu, ss, 1);
        ss += __shfl_xor_sync(0xffffffffu, ss, 2);
        if (act && l == 0) rinv[r] = 1.f / (sqrtf(ss) + 1e-8f);
    }
    __syncthreads();

    // softmax over r per w (max-free) + w12 fused
    const int w3 = t >> 2, l3 = t & 3;
    float a9[9];
    float w12v;
    {
        float e9[9];
        float s = 0.f, w12p = 0.f;
        #pragma unroll
        for (int jj = 0; jj < 9; jj++) {
            int r = l3 * 9 + jj;
            float sraw = Sp[r * WW + w3];
            float v = (sraw >= 0.f) ? sraw : 0.1f * sraw;
            float e = __expf(9.f * v * rinv[r]);
            e9[jj] = e;
            s += e;
            w12p = fmaf(e, sraw, w12p);
        }
        s += __shfl_xor_sync(0xffffffffu, s, 1);
        s += __shfl_xor_sync(0xffffffffu, s, 2);
        w12p += __shfl_xor_sync(0xffffffffu, w12p, 1);
        w12p += __shfl_xor_sync(0xffffffffu, w12p, 2);
        float is = 1.f / s;
        w12v = w12p * is;
        #pragma unroll
        for (int jj = 0; jj < 9; jj++) {
            float a = e9[jj] * is;
            a9[jj] = a;
            At[w3 * AT_STR + l3 * 9 + jj] = a;
        }
    }
    __syncthreads();

    // w2sq = A G A^T quadratic form
    {
        float4 av[9];
        const float4* apv = (const float4*)(At + w3 * AT_STR);
        #pragma unroll
        for (int q = 0; q < 9; q++) av[q] = apv[q];
        float w2p = 0.f;
        #pragma unroll
        for (int jj = 0; jj < 9; jj++) {
            const int k = l3 * 9 + jj;
            const float4* gp = (const float4*)(Gm + k * RR);
            float uacc = 0.f;
            #pragma unroll
            for (int q = 0; q < 9; q++) {
                float4 g = gp[q], a = av[q];
                uacc = fmaf(g.x, a.x, uacc);
                uacc = fmaf(g.y, a.y, uacc);
                uacc = fmaf(g.z, a.z, uacc);
                uacc = fmaf(g.w, a.w, uacc);
            }
            w2p = fmaf(a9[jj], uacc, w2p);
        }
        w2p += __shfl_xor_sync(0xffffffffu, w2p, 1);
        w2p += __shfl_xor_sync(0xffffffffu, w2p, 2);
        if (l3 == 0) {
            float w2 = sqrtf(fmaxf(w2p, 0.f));
            float denom = fmaxf(capnS[w3] * w2, 1e-8f);
            rs[w3] = (w12v / denom) * 6.f;
        }
    }
    __syncthreads();

    // LogSumExp over 48 words (max-free)
    if (t < 32) {
        float s = __expf(rs[t]);
        if (t < 16) s += __expf(rs[32 + t]);
        #pragma unroll
        for (int off = 16; off; off >>= 1)
            s += __shfl_xor_sync(0xffffffffu, s, off);
        if (t == 0)
            out[(size_t)i * NC + c] = logf(s) * (1.f / 6.f);
    }
}

extern "C" void kernel_launch(void* const* d_in, const int* in_sizes, int n_in,
                              void* d_out, int out_size)
{
    const float* images   = (const float*)d_in[0];   // (128, 36, 256) fp32
    const float* captions = (const float*)d_in[1];   // (256, 48, 256) fp32
    float* out = (float*)d_out;                       // (128, 256) fp32

    decomp_kernel<<<512, 256>>>(images, captions);
    capnorm_kernel<<<NC, WW>>>(captions);
    gram_kernel<<<NI, 256>>>(images);

    cudaFuncSetAttribute(gemm_kernel,
                         cudaFuncAttributeMaxDynamicSharedMemorySize, GSMEM_TOTAL);
    dim3 ggrid(NCOLS / 128, MROWS / 128);   // 96 x 36
    gemm_kernel<<<ggrid, GT, GSMEM_TOTAL>>>();

    dim3 egrid(NC, NI);
    epi_kernel<<<egrid, NT>>>(out);
}

// round 7
// speedup vs baseline: 5.4641x; 1.2464x over previous
#include <cuda_runtime.h>
#include <cuda_bf16.h>
#include <math.h>
#include <float.h>
#include <stdint.h>

#define NI 128
#define NC 256
#define RR 36
#define WW 48
#define DD 256

#define MROWS (NI*RR)     // 4608
#define NCOLS (NC*WW)     // 12288

// ---------------- device scratch ----------------
__device__ __align__(16) __nv_bfloat16 g_Ahi[MROWS * DD];
__device__ __align__(16) __nv_bfloat16 g_Alo[MROWS * DD];
__device__ __align__(16) __nv_bfloat16 g_Bhi[NCOLS * DD];
__device__ __align__(16) __nv_bfloat16 g_Blo[NCOLS * DD];
__device__ __align__(16) float g_S[(size_t)MROWS * NCOLS];   // 226 MB
__device__ float g_capnorm[NC * WW];
__device__ __align__(16) float g_gram[NI * RR * RR];

// ---------------- PTX helpers (baseline sm_80 features only) ----------------
__device__ __forceinline__ uint32_t smem_u32(const void* p) {
    uint32_t a;
    asm("{ .reg .u64 t; cvta.to.shared.u64 t, %1; cvt.u32.u64 %0, t; }" : "=r"(a) : "l"(p));
    return a;
}
__device__ __forceinline__ void cpa16(uint32_t dst, const void* src) {
    asm volatile("cp.async.cg.shared.global [%0], [%1], 16;" :: "r"(dst), "l"(src));
}
__device__ __forceinline__ void cpa_commit() {
    asm volatile("cp.async.commit_group;" ::: "memory");
}
template<int N> __device__ __forceinline__ void cpa_wait() {
    asm volatile("cp.async.wait_group %0;" :: "n"(N) : "memory");
}
__device__ __forceinline__ void ldsm4(uint32_t* r, uint32_t addr) {
    asm volatile("ldmatrix.sync.aligned.m8n8.x4.shared.b16 {%0,%1,%2,%3}, [%4];"
                 : "=r"(r[0]), "=r"(r[1]), "=r"(r[2]), "=r"(r[3]) : "r"(addr));
}
__device__ __forceinline__ void mma_bf16(float* d, const uint32_t* a, const uint32_t* b) {
    asm volatile(
        "mma.sync.aligned.m16n8k16.row.col.f32.bf16.bf16.f32 "
        "{%0,%1,%2,%3}, {%4,%5,%6,%7}, {%8,%9}, {%0,%1,%2,%3};"
        : "+f"(d[0]), "+f"(d[1]), "+f"(d[2]), "+f"(d[3])
        : "r"(a[0]), "r"(a[1]), "r"(a[2]), "r"(a[3]), "r"(b[0]), "r"(b[1]));
}

// ---------------- pre-kernels ----------------
__global__ void decomp_kernel(const float* __restrict__ images,
                              const float* __restrict__ captions) {
    int stride = gridDim.x * blockDim.x;
    int g = blockIdx.x * blockDim.x + threadIdx.x;
    for (int idx = g; idx < MROWS * DD; idx += stride) {
        float x = images[idx];
        __nv_bfloat16 h = __float2bfloat16(x);
        g_Ahi[idx] = h;
        g_Alo[idx] = __float2bfloat16(x - __bfloat162float(h));
    }
    for (int idx = g; idx < NCOLS * DD; idx += stride) {
        float x = captions[idx];
        __nv_bfloat16 h = __float2bfloat16(x);
        g_Bhi[idx] = h;
        g_Blo[idx] = __float2bfloat16(x - __bfloat162float(h));
    }
}

__global__ void capnorm_kernel(const float* __restrict__ captions) {
    int c = blockIdx.x, w = threadIdx.x;
    const float4* p = (const float4*)(captions + ((size_t)c * WW + w) * DD);
    float s = 0.f;
    #pragma unroll 8
    for (int j = 0; j < DD / 4; ++j) {
        float4 v = p[j];
        s += v.x * v.x + v.y * v.y + v.z * v.z + v.w * v.w;
    }
    g_capnorm[c * WW + w] = sqrtf(s);
}

#define GIMG_STR 260
__global__ void gram_kernel(const float* __restrict__ images) {
    __shared__ float s_img[RR * GIMG_STR];
    const int i = blockIdx.x;
    const float4* src = (const float4*)(images + (size_t)i * RR * DD);
    for (int idx = threadIdx.x; idx < RR * DD / 4; idx += blockDim.x) {
        float4 v = src[idx];
        int r = idx >> 6;
        int d = (idx & 63) << 2;
        *(float4*)(s_img + r * GIMG_STR + d) = v;
    }
    __syncthreads();
    for (int e = threadIdx.x; e < RR * RR; e += blockDim.x) {
        int k1 = e / RR, k2 = e % RR;
        const float4* p = (const float4*)(s_img + k1 * GIMG_STR);
        const float4* q = (const float4*)(s_img + k2 * GIMG_STR);
        float s = 0.f;
        #pragma unroll 8
        for (int d = 0; d < DD / 4; ++d) {
            float4 a = p[d], b = q[d];
            s = fmaf(a.x, b.x, s); s = fmaf(a.y, b.y, s);
            s = fmaf(a.z, b.z, s); s = fmaf(a.w, b.w, s);
        }
        g_gram[(size_t)i * RR * RR + e] = s;
    }
}

// ---------------- GEMM: S_all = A @ B^T via mma.sync bf16 3-term split ----------------
#define GT 256
#define TSTR_B 80
#define TILE_BYTES (128 * TSTR_B)              // 10240
#define GSMEM_TOTAL (8 * TILE_BYTES)           // 81920

__global__ void __launch_bounds__(GT, 2) gemm_kernel() {
    extern __shared__ char smem[];
    const uint32_t sb = smem_u32(smem);
    const int tid = threadIdx.x;
    const int wid = tid >> 5, lane = tid & 31;
    const int ntile = blockIdx.x;
    const int mtile = blockIdx.y;

    const __nv_bfloat16* gsrc[4] = {
        g_Ahi + (size_t)(mtile * 128) * DD,
        g_Alo + (size_t)(mtile * 128) * DD,
        g_Bhi + (size_t)(ntile * 128) * DD,
        g_Blo + (size_t)(ntile * 128) * DD
    };

    auto issue = [&](int kc) {
        const uint32_t bufbase = sb + (uint32_t)(kc & 1) * 4 * TILE_BYTES;
        #pragma unroll
        for (int p = 0; p < 8; p++) {
            int idx = tid + p * GT;
            int tile = idx >> 9, rem = idx & 511;
            int r = rem >> 2, j = rem & 3;
            const __nv_bfloat16* src = gsrc[tile] + (size_t)r * DD + kc * 32 + j * 8;
            uint32_t dst = bufbase + tile * TILE_BYTES + r * TSTR_B + j * 16;
            cpa16(dst, src);
        }
        cpa_commit();
    };

    const int wm = wid >> 2, wn = wid & 3;

    float acc[4][4][4];
    #pragma unroll
    for (int f = 0; f < 4; f++)
        #pragma unroll
        for (int nf = 0; nf < 4; nf++)
            #pragma unroll
            for (int e = 0; e < 4; e++) acc[f][nf][e] = 0.f;

    issue(0);
    for (int kc = 0; kc < 8; kc++) {
        if (kc < 7) { issue(kc + 1); cpa_wait<1>(); }
        else        { cpa_wait<0>(); }
        __syncthreads();

        const uint32_t abase = sb + (uint32_t)(kc & 1) * 4 * TILE_BYTES;
        const uint32_t bbase = abase + 2 * TILE_BYTES;

        #pragma unroll
        for (int s = 0; s < 2; s++) {
            uint32_t bh[8], bl[8];
            {
                int bn = wn * 32 + (lane & 7) + ((lane >> 4) << 3);
                uint32_t bcol = s * 32 + ((lane >> 3) & 1) * 16;
                #pragma unroll
                for (int g = 0; g < 2; g++) {
                    uint32_t addr = bbase + (uint32_t)(bn + g * 16) * TSTR_B + bcol;
                    ldsm4(&bh[g * 4], addr);
                    ldsm4(&bl[g * 4], addr + TILE_BYTES);
                }
            }
            int ar = wm * 64 + (lane & 15);
            uint32_t acol = s * 32 + (lane >> 4) * 16;
            #pragma unroll
            for (int f = 0; f < 4; f++) {
                uint32_t aaddr = abase + (uint32_t)(ar + f * 16) * TSTR_B + acol;
                uint32_t ah[4], al[4];
                ldsm4(ah, aaddr);
                ldsm4(al, aaddr + TILE_BYTES);
                #pragma unroll
                for (int nf = 0; nf < 4; nf++) {
                    mma_bf16(acc[f][nf], ah, &bh[nf * 2]);
                    mma_bf16(acc[f][nf], ah, &bl[nf * 2]);
                    mma_bf16(acc[f][nf], al, &bh[nf * 2]);
                }
            }
        }
        __syncthreads();
    }

    float* obase = g_S + (size_t)(mtile * 128) * NCOLS + ntile * 128;
    const int r0 = wm * 64 + (lane >> 2);
    const int c0 = wn * 32 + (lane & 3) * 2;
    #pragma unroll
    for (int f = 0; f < 4; f++) {
        #pragma unroll
        for (int nf = 0; nf < 4; nf++) {
            int r = r0 + f * 16, cc = c0 + nf * 8;
            float2 v0 = { acc[f][nf][0], acc[f][nf][1] };
            float2 v1 = { acc[f][nf][2], acc[f][nf][3] };
            *(float2*)(obase + (size_t)r * NCOLS + cc) = v0;
            *(float2*)(obase + (size_t)(r + 8) * NCOLS + cc) = v1;
        }
    }
}

// ---------------- epilogue v2: warp-per-pair, 8 pairs per CTA ----------------
#define ET 256
#define NTILE 1728              // 36*48 floats per S tile
// smem layout (float offsets)
#define EOFF_G    0                         // 1296
#define EOFF_S    1296                      // 8 * 1728 = 13824
#define EOFF_RINV (EOFF_S + 8*NTILE)        // 8*36 = 288
#define EOFF_RS   (EOFF_RINV + 288)         // 8*48 = 384
#define EOFF_CN   (EOFF_RS + 384)           // 8*48 = 384
#define ESMEM_FLOATS (EOFF_CN + 384)        // 16176 floats = 64704 B

extern __shared__ float esm[];

__global__ void __launch_bounds__(ET, 2) epi_kernel(float* __restrict__ out) {
    const int cg = blockIdx.x;      // caption group (8 captions)
    const int i  = blockIdx.y;      // image
    const int t  = threadIdx.x;
    const int lane = t & 31, wj = t >> 5;   // warp j handles caption c0+wj
    const int c0 = cg * 8;

    float* Gs    = esm + EOFF_G;
    float* Stl   = esm + EOFF_S;
    float* rinvS = esm + EOFF_RINV;
    float* rsS   = esm + EOFF_RS;
    float* cnS   = esm + EOFF_CN;

    // ---- cooperative loads ----
    {
        // S tiles: per image-row r, 8 tiles x 12 float4 contiguous in g_S
        const float* srow = g_S + (size_t)(i * RR) * NCOLS + (size_t)c0 * WW;
        for (int idx = t; idx < RR * 96; idx += ET) {
            int r = idx / 96, rem = idx % 96;        // rem: j*12+q
            int j = rem / 12, q = rem % 12;
            float4 v = *(const float4*)(srow + (size_t)r * NCOLS + j * WW + q * 4);
            *(float4*)(Stl + j * NTILE + r * WW + q * 4) = v;
        }
        const float4* gsrc = (const float4*)(g_gram + (size_t)i * RR * RR);
        for (int idx = t; idx < RR * RR / 4; idx += ET)
            *(float4*)(Gs + idx * 4) = gsrc[idx];
        const float* cn = g_capnorm + c0 * WW;
        for (int idx = t; idx < 8 * WW; idx += ET) cnS[idx] = cn[idx];
    }
    __syncthreads();

    // ---- rinv: 288 rows CTA-wide; lane-rotated scalar LDS (bank conflict-free) ----
    for (int row = t; row < 8 * RR; row += ET) {
        int j = row / RR, r = row % RR;
        const float* sp = Stl + j * NTILE + r * WW;
        float ss = 0.f;
        #pragma unroll
        for (int q = 0; q < WW; q++) {
            int w = (q + lane) % WW;        // rotate start per lane
            float v = sp[w];
            v = (v >= 0.f) ? v : 0.1f * v;
            ss = fmaf(v, v, ss);
        }
        rinvS[j * RR + r] = 1.f / (sqrtf(ss) + 1e-8f);
    }
    __syncthreads();

    // ---- per-warp: softmax + w12 + quadratic form over its pair ----
    const float* Sw = Stl + wj * NTILE;
    const float* rv = rinvS + wj * RR;
    const int l3 = lane & 3;        // k-chunk 0..3 (9 rows each)
    const int wl = lane >> 2;       // 0..7 w within group

    #pragma unroll 1
    for (int wg = 0; wg < 6; wg++) {
        const int w = wg * 8 + wl;
        // softmax partials (unnormalized, max-free: |9*shat| <= 9)
        float e9[9];
        float s = 0.f, w12p = 0.f;
        #pragma unroll
        for (int jj = 0; jj < 9; jj++) {
            int r = l3 * 9 + jj;
            float sraw = Sw[r * WW + w];
            float v = (sraw >= 0.f) ? sraw : 0.1f * sraw;
            float e = __expf(9.f * v * rv[r]);
            e9[jj] = e;
            s += e;
            w12p = fmaf(e, sraw, w12p);
        }
        s    += __shfl_xor_sync(0xffffffffu, s, 1);
        s    += __shfl_xor_sync(0xffffffffu, s, 2);
        w12p += __shfl_xor_sync(0xffffffffu, w12p, 1);
        w12p += __shfl_xor_sync(0xffffffffu, w12p, 2);

        // gather full unnormalized e vector (36) via compile-time-indexed shuffles
        float ef[36];
        const int base = lane & ~3;
        #pragma unroll
        for (int q = 0; q < 9; q++) {
            ef[0 * 9 + q]  = __shfl_sync(0xffffffffu, e9[q], base + 0);
            ef[1 * 9 + q]  = __shfl_sync(0xffffffffu, e9[q], base + 1);
            ef[2 * 9 + q]  = __shfl_sync(0xffffffffu, e9[q], base + 2);
            ef[3 * 9 + q]  = __shfl_sync(0xffffffffu, e9[q], base + 3);
        }

        // quadratic form partial: sum over own 9 k-rows of e9[jj] * (G[k,:] . ef)
        float w2p = 0.f;
        #pragma unroll
        for (int jj = 0; jj < 9; jj++) {
            const int k = l3 * 9 + jj;
            const float4* gp = (const float4*)(Gs + k * RR);
            float uacc = 0.f;
            #pragma unroll
            for (int q = 0; q < 9; q++) {
                float4 g = gp[q];
                uacc = fmaf(g.x, ef[q * 4 + 0], uacc);
                uacc = fmaf(g.y, ef[q * 4 + 1], uacc);
                uacc = fmaf(g.z, ef[q * 4 + 2], uacc);
                uacc = fmaf(g.w, ef[q * 4 + 3], uacc);
            }
            w2p = fmaf(e9[jj], uacc, w2p);
        }
        w2p += __shfl_xor_sync(0xffffffffu, w2p, 1);
        w2p += __shfl_xor_sync(0xffffffffu, w2p, 2);

        if (l3 == 0) {
            float is = 1.f / s;
            float w12v = w12p * is;                         // = sum(a*sraw)
            float w2v = sqrtf(fmaxf(w2p, 0.f)) * is;        // = ||wctx||
            float denom = fmaxf(cnS[wj * WW + w] * w2v, 1e-8f);
            rsS[wj * WW + w] = (w12v / denom) * 6.f;
        }
    }
    __syncwarp();

    // ---- per-warp LogSumExp over 48 words (max-free: |rs| <= 6) ----
    {
        const float* r = rsS + wj * WW;
        float s = __expf(r[lane]);
        if (lane < 16) s += __expf(r[32 + lane]);
        #pragma unroll
        for (int off = 16; off; off >>= 1)
            s += __shfl_xor_sync(0xffffffffu, s, off);
        if (lane == 0)
            out[(size_t)i * NC + (c0 + wj)] = logf(s) * (1.f / 6.f);
    }
}

extern "C" void kernel_launch(void* const* d_in, const int* in_sizes, int n_in,
                              void* d_out, int out_size)
{
    const float* images   = (const float*)d_in[0];   // (128, 36, 256) fp32
    const float* captions = (const float*)d_in[1];   // (256, 48, 256) fp32
    float* out = (float*)d_out;                       // (128, 256) fp32

    decomp_kernel<<<512, 256>>>(images, captions);
    capnorm_kernel<<<NC, WW>>>(captions);
    gram_kernel<<<NI, 256>>>(images);

    cudaFuncSetAttribute(gemm_kernel,
                         cudaFuncAttributeMaxDynamicSharedMemorySize, GSMEM_TOTAL);
    dim3 ggrid(NCOLS / 128, MROWS / 128);   // 96 x 36
    gemm_kernel<<<ggrid, GT, GSMEM_TOTAL>>>();

    cudaFuncSetAttribute(epi_kernel,
                         cudaFuncAttributeMaxDynamicSharedMemorySize,
                         ESMEM_FLOATS * (int)sizeof(float));
    dim3 egrid(NC / 8, NI);                 // 32 x 128
    epi_kernel<<<egrid, ET, ESMEM_FLOATS * sizeof(float)>>>(out);
}